// round 10
// baseline (speedup 1.0000x reference)
#include <cuda_runtime.h>
#include <cuda_fp16.h>
#include <float.h>
#include <math.h>
#include <cstdint>

// Problem constants
#define BATCH  32
#define SEQ    577
#define DMODEL 768
#define NHEAD  12
#define HDIM   64
#define MROWS  (BATCH * SEQ)                  // 18464
#define ELEMS  (MROWS * DMODEL)               // 14,180,352
#define WSZ    (DMODEL * DMODEL)              // 589,824

// fp16 scratch
__device__ __half g_xh[ELEMS];      // x
__device__ __half g_ch[ELEMS];      // ctx (attention output)
__device__ __half g_wh[4 * WSZ];    // Wq, Wk, Wv, Wo (contiguous)
__device__ __half g_Qh[ELEMS];      // [B,H,N,64]
__device__ __half g_Kh[ELEMS];
__device__ __half g_Vh[ELEMS];

// ---------------------------------------------------------------------------
// PTX helpers (plain sm_103-safe)
// ---------------------------------------------------------------------------
__device__ __forceinline__ uint32_t smem_u32(const void* p) {
    uint32_t a;
    asm("{ .reg .u64 t; cvta.to.shared.u64 t, %1; cvt.u32.u64 %0, t; }" : "=r"(a) : "l"(p));
    return a;
}
__device__ __forceinline__ void cp_async16(uint32_t dst, const void* src, bool valid) {
    int sz = valid ? 16 : 0;
    asm volatile("cp.async.cg.shared.global [%0], [%1], 16, %2;"
                 :: "r"(dst), "l"(src), "r"(sz));
}
#define CP_COMMIT() asm volatile("cp.async.commit_group;" ::: "memory")
#define CP_WAIT(N)  asm volatile("cp.async.wait_group %0;" :: "n"(N) : "memory")

__device__ __forceinline__ void ldsm_x4(uint32_t* r, uint32_t addr) {
    asm volatile("ldmatrix.sync.aligned.m8n8.x4.shared.b16 {%0,%1,%2,%3}, [%4];"
                 : "=r"(r[0]), "=r"(r[1]), "=r"(r[2]), "=r"(r[3]) : "r"(addr));
}
__device__ __forceinline__ void ldsm_x4t(uint32_t* r, uint32_t addr) {
    asm volatile("ldmatrix.sync.aligned.m8n8.x4.trans.shared.b16 {%0,%1,%2,%3}, [%4];"
                 : "=r"(r[0]), "=r"(r[1]), "=r"(r[2]), "=r"(r[3]) : "r"(addr));
}
__device__ __forceinline__ void mma16816h(float* c, const uint32_t* a, const uint32_t* b) {
    asm volatile(
        "mma.sync.aligned.m16n8k16.row.col.f32.f16.f16.f32 "
        "{%0,%1,%2,%3}, {%4,%5,%6,%7}, {%8,%9}, {%0,%1,%2,%3};"
        : "+f"(c[0]), "+f"(c[1]), "+f"(c[2]), "+f"(c[3])
        : "r"(a[0]), "r"(a[1]), "r"(a[2]), "r"(a[3]), "r"(b[0]), "r"(b[1]));
}
__device__ __forceinline__ uint32_t h2_bits(float a, float b) {
    __half2 v = __floats2half2_rn(a, b);
    return *(uint32_t*)&v;
}

// ---------------------------------------------------------------------------
// Fused fp32 -> fp16 conversion: x then Wq,Wk,Wv,Wo (one launch).
// ---------------------------------------------------------------------------
#define XN4 (ELEMS / 4)     // 3,545,088
#define WN4 (WSZ / 4)       // 147,456
#define CVT_TOTAL (XN4 + 4 * WN4)

__global__ void to_fp16_all(const float* __restrict__ x,  const float* __restrict__ wq,
                            const float* __restrict__ wk, const float* __restrict__ wv,
                            const float* __restrict__ wo)
{
    int i = blockIdx.x * blockDim.x + threadIdx.x;
    if (i >= CVT_TOTAL) return;
    const float* src;
    __half* dst;
    int j;
    if (i < XN4) { src = x; dst = g_xh; j = i; }
    else {
        int r = i - XN4;
        int m = r / WN4;
        j = r - m * WN4;
        src = (m == 0) ? wq : (m == 1) ? wk : (m == 2) ? wv : wo;
        dst = g_wh + (size_t)m * WSZ;
    }
    float4 v = ((const float4*)src)[j];
    ((uint32_t*)dst)[2 * j]     = h2_bits(v.x, v.y);
    ((uint32_t*)dst)[2 * j + 1] = h2_bits(v.z, v.w);
}

// ---------------------------------------------------------------------------
// fp16 NT GEMM (mma.sync m16n8k16, fp32 accum). CTA tile 128x256, 8 warps
// (2m x 4n), warp tile 64x64, K blocked by 32, 3-stage cp.async pipeline.
// QKV=1: fused QKV. grid.x = 9 (3 n-tiles per matrix); A = g_xh.
//        Epilogue: bias, fp16 scatter into g_{Q,K,V}h as [B,H,N,64].
// QKV=0: out-projection. grid.x = 3; A = g_ch; fp32 store to outp.
// ---------------------------------------------------------------------------
#define BKG    32
#define NKB    (DMODEL / BKG)         // 24
#define ROWB   80                     // 32 fp16 = 64B + 16B pad
#define AMATB  (128 * ROWB)           // 10240
#define BMATB  (256 * ROWB)           // 20480
#define STAGEB (AMATB + BMATB)        // 30720
#define GEMM_SMEM (3 * STAGEB)        // 92160

extern __shared__ char dynsmem[];

template<int QKV>
__global__ __launch_bounds__(256)
void gemm_tc(const float* __restrict__ b0, const float* __restrict__ b1,
             const float* __restrict__ b2, float* __restrict__ outp)
{
    const int mat  = QKV ? (blockIdx.x / 3) : 3;
    const int colb = QKV ? ((blockIdx.x % 3) * 256) : (blockIdx.x * 256);
    const __half* A = QKV ? g_xh : g_ch;
    const __half* B = g_wh + (size_t)mat * WSZ;
    const float* bias = QKV ? (mat == 0 ? b0 : mat == 1 ? b1 : b2) : b0;

    const uint32_t sb = smem_u32(dynsmem);
    const int tid  = threadIdx.x;
    const int wid  = tid >> 5;
    const int lane = tid & 31;
    const int wm   = wid & 1;          // 2 m-slabs of 64
    const int wn   = wid >> 1;         // 4 n-slabs of 64
    const int block_m = blockIdx.y * 128;

    float c[4][8][4];
#pragma unroll
    for (int mi = 0; mi < 4; mi++)
#pragma unroll
        for (int ni = 0; ni < 8; ni++)
#pragma unroll
            for (int r = 0; r < 4; r++) c[mi][ni][r] = 0.f;

    auto issue_load = [&](int kb, int buf) {
        const int k0 = kb * BKG;
        const uint32_t stg = sb + buf * STAGEB;
#pragma unroll
        for (int it = 0; it < 6; it++) {
            int idx = tid + it * 256;          // 0..1535
            if (idx < 512) {                   // A: 128 rows x 4 chunks
                int row = idx >> 2, cc = idx & 3;
                int gr = block_m + row;
                bool valid = gr < MROWS;
                if (!valid) gr = 0;
                cp_async16(stg + row * ROWB + cc * 16,
                           A + (size_t)gr * DMODEL + k0 + cc * 8, valid);
            } else {                           // B: 256 rows x 4 chunks
                int r = idx - 512;
                int row = r >> 2, cc = r & 3;
                cp_async16(stg + AMATB + row * ROWB + cc * 16,
                           B + (size_t)(colb + row) * DMODEL + k0 + cc * 8, true);
            }
        }
        CP_COMMIT();
    };

    issue_load(0, 0);
    issue_load(1, 1);

    for (int kb = 0; kb < NKB; kb++) {
        if (kb < NKB - 1) { CP_WAIT(1); } else { CP_WAIT(0); }
        __syncthreads();
        if (kb + 2 < NKB) issue_load(kb + 2, (kb + 2) % 3);

        const uint32_t stg = sb + (kb % 3) * STAGEB;
#pragma unroll
        for (int kt = 0; kt < 2; kt++) {
            uint32_t afr[4][4];
            uint32_t bfr[4][4];
#pragma unroll
            for (int mi = 0; mi < 4; mi++) {
                int row  = wm * 64 + mi * 16 + (lane & 15);
                int kcol = kt * 16 + (lane >> 4) * 8;
                ldsm_x4(afr[mi], stg + row * ROWB + kcol * 2);
            }
#pragma unroll
            for (int nip = 0; nip < 4; nip++) {
                int brow = wn * 64 + nip * 16 + (lane >> 4) * 8 + (lane & 7);
                uint32_t a = stg + AMATB + brow * ROWB
                           + kt * 32 + ((lane >> 3) & 1) * 16;
                ldsm_x4(bfr[nip], a);
            }
#pragma unroll
            for (int mi = 0; mi < 4; mi++)
#pragma unroll
                for (int nip = 0; nip < 4; nip++) {
                    mma16816h(c[mi][2 * nip],     afr[mi], bfr[nip]);
                    mma16816h(c[mi][2 * nip + 1], afr[mi], bfr[nip] + 2);
                }
        }
        __syncthreads();
    }

    __half* qkvd = (mat == 0) ? g_Qh : (mat == 1) ? g_Kh : g_Vh;
#pragma unroll
    for (int mi = 0; mi < 4; mi++) {
#pragma unroll
        for (int half = 0; half < 2; half++) {
            int gm = block_m + wm * 64 + mi * 16 + (lane >> 2) + half * 8;
            if (gm >= MROWS) continue;
            int b_idx = gm / SEQ;
            int n_idx = gm - b_idx * SEQ;
#pragma unroll
            for (int ni = 0; ni < 8; ni++) {
                int colg = colb + wn * 64 + ni * 8 + 2 * (lane & 3);
                float2 bv = *(const float2*)(bias + colg);
                float v0 = c[mi][ni][half * 2 + 0] + bv.x;
                float v1 = c[mi][ni][half * 2 + 1] + bv.y;
                if (QKV) {
                    int h = colg >> 6, hd = colg & 63;
                    size_t off = (((size_t)b_idx * NHEAD + h) * SEQ + n_idx) * HDIM + hd;
                    *(uint32_t*)(qkvd + off) = h2_bits(v0, v1);
                } else {
                    *(float2*)(outp + (size_t)gm * DMODEL + colg) = make_float2(v0, v1);
                }
            }
        }
    }
}

// ---------------------------------------------------------------------------
// MMA flash attention (fp16): anti-causal (k >= q), scale 1/sqrt(768).
// CTA = (b,h, 128-query tile); 8 warps x 16 rows; 64-key tiles, cp.async
// double-buffered. Per-warp whole-tile skip when all keys < warp's rows.
// ---------------------------------------------------------------------------
#define KROWB  144                    // 64 fp16 = 128B + 16B pad
#define QTILEB (128 * KROWB)          // 18432
#define KTILEB (64 * KROWB)           // 9216
#define KVBUF  (2 * KTILEB)           // K + V
#define ATT_SMEM (QTILEB + 2 * KVBUF) // 55296

__global__ __launch_bounds__(256, 2)
void attn_mma()
{
    const int bh  = blockIdx.y;
    const int q0  = blockIdx.x * 128;
    const int tid = threadIdx.x;
    const int wid = tid >> 5;
    const int lane = tid & 31;
    const uint32_t sb = smem_u32(dynsmem);
    const size_t base = (size_t)bh * SEQ * HDIM;
    const float SCALE = 0.03608439182435161f;   // 1/sqrt(768)

    // Q tile: 128 rows x 8 chunks = 1024 over 256 threads
#pragma unroll
    for (int it = 0; it < 4; it++) {
        int idx = tid + it * 256;
        int row = idx >> 3;
        int cc  = idx & 7;
        int gq  = q0 + row;
        bool valid = gq < SEQ;
        cp_async16(sb + row * KROWB + cc * 16,
                   g_Qh + base + (size_t)(valid ? gq : 0) * HDIM + cc * 8, valid);
    }
    CP_COMMIT();

    auto issue_kv = [&](int kc, int stage) {
#pragma unroll
        for (int it = 0; it < 4; it++) {
            int idx = tid + it * 256;      // 0..1023
            int m   = idx >> 9;            // 0 = K, 1 = V
            int row = (idx >> 3) & 63;
            int cc  = idx & 7;
            int gk  = kc + row;
            bool valid = gk < SEQ;
            const __half* sp = m ? g_Vh : g_Kh;
            cp_async16(sb + QTILEB + stage * KVBUF + m * KTILEB + row * KROWB + cc * 16,
                       sp + base + (size_t)(valid ? gk : 0) * HDIM + cc * 8, valid);
        }
        CP_COMMIT();
    };
    issue_kv(q0, 0);

    // Q fragments (warp wid owns rows wid*16 .. wid*16+15)
    CP_WAIT(1);
    __syncthreads();
    uint32_t qh[4][4];
#pragma unroll
    for (int ks = 0; ks < 4; ks++)
        ldsm_x4(qh[ks], sb + (wid * 16 + (lane & 15)) * KROWB + ks * 32 + (lane >> 4) * 16);

    float o[8][4];
#pragma unroll
    for (int vi = 0; vi < 8; vi++)
#pragma unroll
        for (int r = 0; r < 4; r++) o[vi][r] = 0.f;
    float m0 = -FLT_MAX, m1 = -FLT_MAX, l0 = 0.f, l1 = 0.f;

    const int wrow0 = q0 + wid * 16;          // warp's first query row
    const int qrow0 = wrow0 + (lane >> 2);
    const int nkt = (SEQ - q0 + 63) / 64;

    for (int kt = 0; kt < nkt; kt++) {
        const int kc = q0 + kt * 64;
        const int stage = kt & 1;
        CP_WAIT(0);
        __syncthreads();
        if (kt + 1 < nkt) issue_kv(kc + 64, stage ^ 1);
        const uint32_t kb = sb + QTILEB + stage * KVBUF;

        // Whole tile below this warp's rows -> fully masked -> skip
        if (kc + 64 > wrow0) {
            // ---- S = Q K^T
            float s[8][4];
#pragma unroll
            for (int ni = 0; ni < 8; ni++)
#pragma unroll
                for (int r = 0; r < 4; r++) s[ni][r] = 0.f;
#pragma unroll
            for (int ks = 0; ks < 4; ks++) {
#pragma unroll
                for (int nip = 0; nip < 4; nip++) {
                    uint32_t kf[4];
                    uint32_t a = kb + (nip * 16 + (lane >> 4) * 8 + (lane & 7)) * KROWB
                               + ks * 32 + ((lane >> 3) & 1) * 16;
                    ldsm_x4(kf, a);
                    mma16816h(s[2 * nip],     qh[ks], kf);
                    mma16816h(s[2 * nip + 1], qh[ks], kf + 2);
                }
            }

            // ---- mask (tile overlaps diagonal for this warp, or SEQ edge)
            if (kc < wrow0 + 16 || kc + 64 > SEQ) {
#pragma unroll
                for (int ni = 0; ni < 8; ni++)
#pragma unroll
                    for (int r = 0; r < 4; r++) {
                        int key = kc + ni * 8 + 2 * (lane & 3) + (r & 1);
                        int qq  = qrow0 + (r >> 1) * 8;
                        if (key < qq || key >= SEQ) s[ni][r] = -FLT_MAX;
                    }
            }

            // ---- online softmax
            float t0 = -FLT_MAX, t1 = -FLT_MAX;
#pragma unroll
            for (int ni = 0; ni < 8; ni++) {
                t0 = fmaxf(t0, fmaxf(s[ni][0], s[ni][1]));
                t1 = fmaxf(t1, fmaxf(s[ni][2], s[ni][3]));
            }
            t0 = fmaxf(t0, __shfl_xor_sync(0xffffffffu, t0, 1));
            t0 = fmaxf(t0, __shfl_xor_sync(0xffffffffu, t0, 2));
            t1 = fmaxf(t1, __shfl_xor_sync(0xffffffffu, t1, 1));
            t1 = fmaxf(t1, __shfl_xor_sync(0xffffffffu, t1, 2));
            float mn0 = fmaxf(m0, t0), mn1 = fmaxf(m1, t1);
            float c0 = __expf((m0 - mn0) * SCALE);
            float c1 = __expf((m1 - mn1) * SCALE);
            m0 = mn0; m1 = mn1;
            l0 *= c0;  l1 *= c1;
#pragma unroll
            for (int vi = 0; vi < 8; vi++) {
                o[vi][0] *= c0; o[vi][1] *= c0;
                o[vi][2] *= c1; o[vi][3] *= c1;
            }

            // ---- P = exp, pack fp16 a-fragments
            uint32_t pa[4][4];
#pragma unroll
            for (int ni = 0; ni < 8; ni++) {
                float p0 = __expf((s[ni][0] - m0) * SCALE);
                float p1 = __expf((s[ni][1] - m0) * SCALE);
                float p2 = __expf((s[ni][2] - m1) * SCALE);
                float p3 = __expf((s[ni][3] - m1) * SCALE);
                l0 += p0 + p1;  l1 += p2 + p3;
                int kj = ni >> 1;
                int rg = (ni & 1) * 2;
                pa[kj][rg]     = h2_bits(p0, p1);
                pa[kj][rg + 1] = h2_bits(p2, p3);
            }

            // ---- O += P V  (V frags via ldmatrix.trans)
#pragma unroll
            for (int kj = 0; kj < 4; kj++) {
#pragma unroll
                for (int vip = 0; vip < 4; vip++) {
                    uint32_t vf[4];
                    uint32_t a = kb + KTILEB
                               + (kj * 16 + ((lane >> 3) & 1) * 8 + (lane & 7)) * KROWB
                               + vip * 32 + (lane >> 4) * 16;
                    ldsm_x4t(vf, a);
                    mma16816h(o[2 * vip],     pa[kj], vf);
                    mma16816h(o[2 * vip + 1], pa[kj], vf + 2);
                }
            }
        }
    }

    // ---- epilogue
    l0 += __shfl_xor_sync(0xffffffffu, l0, 1);
    l0 += __shfl_xor_sync(0xffffffffu, l0, 2);
    l1 += __shfl_xor_sync(0xffffffffu, l1, 1);
    l1 += __shfl_xor_sync(0xffffffffu, l1, 2);
    float inv0 = 1.f / l0, inv1 = 1.f / l1;

    const int b = bh / NHEAD, h = bh - b * NHEAD;
#pragma unroll
    for (int half = 0; half < 2; half++) {
        int q = q0 + wid * 16 + (lane >> 2) + half * 8;
        if (q >= SEQ) continue;
        size_t rowb = ((size_t)(b * SEQ + q)) * DMODEL + h * HDIM;
        float inv = half ? inv1 : inv0;
#pragma unroll
        for (int vi = 0; vi < 8; vi++) {
            int d = vi * 8 + 2 * (lane & 3);
            *(uint32_t*)(g_ch + rowb + d) =
                h2_bits(o[vi][half * 2 + 0] * inv, o[vi][half * 2 + 1] * inv);
        }
    }
}

// ---------------------------------------------------------------------------
extern "C" void kernel_launch(void* const* d_in, const int* in_sizes, int n_in,
                              void* d_out, int out_size)
{
    (void)in_sizes; (void)n_in; (void)out_size;
    const float* x  = (const float*)d_in[0];
    const float* Wq = (const float*)d_in[1];
    const float* bq = (const float*)d_in[2];
    const float* Wk = (const float*)d_in[3];
    const float* bk = (const float*)d_in[4];
    const float* Wv = (const float*)d_in[5];
    const float* bv = (const float*)d_in[6];
    const float* Wo = (const float*)d_in[7];
    const float* bo = (const float*)d_in[8];
    float* out = (float*)d_out;

    cudaFuncSetAttribute(gemm_tc<1>, cudaFuncAttributeMaxDynamicSharedMemorySize, GEMM_SMEM);
    cudaFuncSetAttribute(gemm_tc<0>, cudaFuncAttributeMaxDynamicSharedMemorySize, GEMM_SMEM);
    cudaFuncSetAttribute(attn_mma,   cudaFuncAttributeMaxDynamicSharedMemorySize, ATT_SMEM);

    // Single fused conversion launch
    to_fp16_all<<<(CVT_TOTAL + 255) / 256, 256>>>(x, Wq, Wk, Wv, Wo);

    // Fused QKV projection (9 n-tiles of 256 = 3 matrices x 3)
    gemm_tc<1><<<dim3(9, (MROWS + 127) / 128), 256, GEMM_SMEM>>>(bq, bk, bv, nullptr);

    // MMA flash attention (128-query tiles)
    attn_mma<<<dim3((SEQ + 127) / 128, BATCH * NHEAD), 256, ATT_SMEM>>>();

    // Output projection (3 n-tiles of 256)
    gemm_tc<0><<<dim3(3, (MROWS + 127) / 128), 256, GEMM_SMEM>>>(bo, nullptr, nullptr, out);
}

// round 11
// speedup vs baseline: 1.1966x; 1.1966x over previous
#include <cuda_runtime.h>
#include <cuda_fp16.h>
#include <float.h>
#include <math.h>
#include <cstdint>

// Problem constants
#define BATCH  32
#define SEQ    577
#define DMODEL 768
#define NHEAD  12
#define HDIM   64
#define MROWS  (BATCH * SEQ)                  // 18464
#define ELEMS  (MROWS * DMODEL)               // 14,180,352
#define WSZ    (DMODEL * DMODEL)              // 589,824

// fp16 scratch
__device__ __half g_xh[ELEMS];      // x
__device__ __half g_ch[ELEMS];      // ctx (attention output)
__device__ __half g_wh[4 * WSZ];    // Wq, Wk, Wv, Wo (contiguous)
__device__ __half g_Qh[ELEMS];      // [B,H,N,64]
__device__ __half g_Kh[ELEMS];
__device__ __half g_Vh[ELEMS];

// ---------------------------------------------------------------------------
// PTX helpers (plain sm_103-safe)
// ---------------------------------------------------------------------------
__device__ __forceinline__ uint32_t smem_u32(const void* p) {
    uint32_t a;
    asm("{ .reg .u64 t; cvta.to.shared.u64 t, %1; cvt.u32.u64 %0, t; }" : "=r"(a) : "l"(p));
    return a;
}
__device__ __forceinline__ void cp_async16(uint32_t dst, const void* src, bool valid) {
    int sz = valid ? 16 : 0;
    asm volatile("cp.async.cg.shared.global [%0], [%1], 16, %2;"
                 :: "r"(dst), "l"(src), "r"(sz));
}
#define CP_COMMIT() asm volatile("cp.async.commit_group;" ::: "memory")
#define CP_WAIT(N)  asm volatile("cp.async.wait_group %0;" :: "n"(N) : "memory")

__device__ __forceinline__ void ldsm_x4(uint32_t* r, uint32_t addr) {
    asm volatile("ldmatrix.sync.aligned.m8n8.x4.shared.b16 {%0,%1,%2,%3}, [%4];"
                 : "=r"(r[0]), "=r"(r[1]), "=r"(r[2]), "=r"(r[3]) : "r"(addr));
}
__device__ __forceinline__ void ldsm_x4t(uint32_t* r, uint32_t addr) {
    asm volatile("ldmatrix.sync.aligned.m8n8.x4.trans.shared.b16 {%0,%1,%2,%3}, [%4];"
                 : "=r"(r[0]), "=r"(r[1]), "=r"(r[2]), "=r"(r[3]) : "r"(addr));
}
__device__ __forceinline__ void mma16816h(float* c, const uint32_t* a, const uint32_t* b) {
    asm volatile(
        "mma.sync.aligned.m16n8k16.row.col.f32.f16.f16.f32 "
        "{%0,%1,%2,%3}, {%4,%5,%6,%7}, {%8,%9}, {%0,%1,%2,%3};"
        : "+f"(c[0]), "+f"(c[1]), "+f"(c[2]), "+f"(c[3])
        : "r"(a[0]), "r"(a[1]), "r"(a[2]), "r"(a[3]), "r"(b[0]), "r"(b[1]));
}
__device__ __forceinline__ uint32_t h2_bits(float a, float b) {
    __half2 v = __floats2half2_rn(a, b);
    return *(uint32_t*)&v;
}

// ---------------------------------------------------------------------------
// Fused fp32 -> fp16 conversion: x then Wq,Wk,Wv,Wo (one launch).
// ---------------------------------------------------------------------------
#define XN4 (ELEMS / 4)     // 3,545,088
#define WN4 (WSZ / 4)       // 147,456
#define CVT_TOTAL (XN4 + 4 * WN4)

__global__ void to_fp16_all(const float* __restrict__ x,  const float* __restrict__ wq,
                            const float* __restrict__ wk, const float* __restrict__ wv,
                            const float* __restrict__ wo)
{
    int i = blockIdx.x * blockDim.x + threadIdx.x;
    if (i >= CVT_TOTAL) return;
    const float* src;
    __half* dst;
    int j;
    if (i < XN4) { src = x; dst = g_xh; j = i; }
    else {
        int r = i - XN4;
        int m = r / WN4;
        j = r - m * WN4;
        src = (m == 0) ? wq : (m == 1) ? wk : (m == 2) ? wv : wo;
        dst = g_wh + (size_t)m * WSZ;
    }
    float4 v = ((const float4*)src)[j];
    ((uint32_t*)dst)[2 * j]     = h2_bits(v.x, v.y);
    ((uint32_t*)dst)[2 * j + 1] = h2_bits(v.z, v.w);
}

// ---------------------------------------------------------------------------
// fp16 NT GEMM (mma.sync m16n8k16, fp32 accum).
// CTA tile 128x128, 4 warps (2m x 2n), warp tile 64x64.
// K blocked by 64 (12 k-blocks), 3-stage cp.async, 2 CTAs/SM.
// QKV=1: fused QKV. grid.x = 18 (3 mats x 6 n-tiles); A = g_xh.
//        Epilogue: bias, fp16 scatter into g_{Q,K,V}h as [B,H,N,64].
// QKV=0: out-projection. grid.x = 6; A = g_ch; fp32 store to outp.
// ---------------------------------------------------------------------------
#define BKG    64
#define NKB    (DMODEL / BKG)         // 12
#define ROWB   144                    // 64 fp16 = 128B + 16B pad
#define AMATB  (128 * ROWB)           // 18432
#define STAGEB (2 * AMATB)            // 36864 (A + B)
#define GEMM_SMEM (3 * STAGEB)        // 110592  -> 2 CTAs/SM

extern __shared__ char dynsmem[];

template<int QKV>
__global__ __launch_bounds__(128)
void gemm_tc(const float* __restrict__ b0, const float* __restrict__ b1,
             const float* __restrict__ b2, float* __restrict__ outp)
{
    const int mat  = QKV ? (blockIdx.x / 6) : 3;
    const int colb = QKV ? ((blockIdx.x % 6) * 128) : (blockIdx.x * 128);
    const __half* A = QKV ? g_xh : g_ch;
    const __half* B = g_wh + (size_t)mat * WSZ;
    const float* bias = QKV ? (mat == 0 ? b0 : mat == 1 ? b1 : b2) : b0;

    const uint32_t sb = smem_u32(dynsmem);
    const int tid  = threadIdx.x;
    const int wid  = tid >> 5;
    const int lane = tid & 31;
    const int wm   = wid & 1;          // 2 m-slabs of 64
    const int wn   = wid >> 1;         // 2 n-slabs of 64
    const int block_m = blockIdx.y * 128;

    float c[4][8][4];
#pragma unroll
    for (int mi = 0; mi < 4; mi++)
#pragma unroll
        for (int ni = 0; ni < 8; ni++)
#pragma unroll
            for (int r = 0; r < 4; r++) c[mi][ni][r] = 0.f;

    auto issue_load = [&](int kb, int buf) {
        const int k0 = kb * BKG;
        const uint32_t stg = sb + buf * STAGEB;
#pragma unroll
        for (int it = 0; it < 16; it++) {
            int idx = tid + it * 128;          // 0..2047
            int m   = idx >> 10;               // 0 = A, 1 = B
            int row = (idx >> 3) & 127;
            int cc  = idx & 7;
            if (m == 0) {
                int gr = block_m + row;
                bool valid = gr < MROWS;
                if (!valid) gr = 0;
                cp_async16(stg + row * ROWB + cc * 16,
                           A + (size_t)gr * DMODEL + k0 + cc * 8, valid);
            } else {
                cp_async16(stg + AMATB + row * ROWB + cc * 16,
                           B + (size_t)(colb + row) * DMODEL + k0 + cc * 8, true);
            }
        }
        CP_COMMIT();
    };

    issue_load(0, 0);
    issue_load(1, 1);

    for (int kb = 0; kb < NKB; kb++) {
        if (kb < NKB - 1) { CP_WAIT(1); } else { CP_WAIT(0); }
        __syncthreads();   // also guards next issue vs previous compute
        if (kb + 2 < NKB) issue_load(kb + 2, (kb + 2) % 3);

        const uint32_t stg = sb + (kb % 3) * STAGEB;
#pragma unroll
        for (int kt = 0; kt < 4; kt++) {
            uint32_t afr[4][4];
            uint32_t bfr[4][4];
#pragma unroll
            for (int mi = 0; mi < 4; mi++) {
                int row  = wm * 64 + mi * 16 + (lane & 15);
                int kcol = kt * 16 + (lane >> 4) * 8;
                ldsm_x4(afr[mi], stg + row * ROWB + kcol * 2);
            }
#pragma unroll
            for (int nip = 0; nip < 4; nip++) {
                int brow = wn * 64 + nip * 16 + (lane >> 4) * 8 + (lane & 7);
                ldsm_x4(bfr[nip], stg + AMATB + brow * ROWB
                                  + kt * 32 + ((lane >> 3) & 1) * 16);
            }
#pragma unroll
            for (int mi = 0; mi < 4; mi++)
#pragma unroll
                for (int nip = 0; nip < 4; nip++) {
                    mma16816h(c[mi][2 * nip],     afr[mi], bfr[nip]);
                    mma16816h(c[mi][2 * nip + 1], afr[mi], bfr[nip] + 2);
                }
        }
    }

    __half* qkvd = (mat == 0) ? g_Qh : (mat == 1) ? g_Kh : g_Vh;
#pragma unroll
    for (int mi = 0; mi < 4; mi++) {
#pragma unroll
        for (int half = 0; half < 2; half++) {
            int gm = block_m + wm * 64 + mi * 16 + (lane >> 2) + half * 8;
            if (gm >= MROWS) continue;
            int b_idx = gm / SEQ;
            int n_idx = gm - b_idx * SEQ;
#pragma unroll
            for (int ni = 0; ni < 8; ni++) {
                int colg = colb + wn * 64 + ni * 8 + 2 * (lane & 3);
                float2 bv = *(const float2*)(bias + colg);
                float v0 = c[mi][ni][half * 2 + 0] + bv.x;
                float v1 = c[mi][ni][half * 2 + 1] + bv.y;
                if (QKV) {
                    int h = colg >> 6, hd = colg & 63;
                    size_t off = (((size_t)b_idx * NHEAD + h) * SEQ + n_idx) * HDIM + hd;
                    *(uint32_t*)(qkvd + off) = h2_bits(v0, v1);
                } else {
                    *(float2*)(outp + (size_t)gm * DMODEL + colg) = make_float2(v0, v1);
                }
            }
        }
    }
}

// ---------------------------------------------------------------------------
// MMA flash attention (fp16): anti-causal (k >= q), scale 1/sqrt(768).
// CTA = (b,h, 128-query tile); 8 warps x 16 rows; 64-key tiles, cp.async
// double-buffered. Per-warp whole-tile skip when all keys < warp's rows.
// ---------------------------------------------------------------------------
#define KROWB  144                    // 64 fp16 = 128B + 16B pad
#define QTILEB (128 * KROWB)          // 18432
#define KTILEB (64 * KROWB)           // 9216
#define KVBUF  (2 * KTILEB)           // K + V
#define ATT_SMEM (QTILEB + 2 * KVBUF) // 55296

__global__ __launch_bounds__(256, 2)
void attn_mma()
{
    const int bh  = blockIdx.y;
    const int q0  = blockIdx.x * 128;
    const int tid = threadIdx.x;
    const int wid = tid >> 5;
    const int lane = tid & 31;
    const uint32_t sb = smem_u32(dynsmem);
    const size_t base = (size_t)bh * SEQ * HDIM;
    const float SCALE = 0.03608439182435161f;   // 1/sqrt(768)

    // Q tile: 128 rows x 8 chunks = 1024 over 256 threads
#pragma unroll
    for (int it = 0; it < 4; it++) {
        int idx = tid + it * 256;
        int row = idx >> 3;
        int cc  = idx & 7;
        int gq  = q0 + row;
        bool valid = gq < SEQ;
        cp_async16(sb + row * KROWB + cc * 16,
                   g_Qh + base + (size_t)(valid ? gq : 0) * HDIM + cc * 8, valid);
    }
    CP_COMMIT();

    auto issue_kv = [&](int kc, int stage) {
#pragma unroll
        for (int it = 0; it < 4; it++) {
            int idx = tid + it * 256;      // 0..1023
            int m   = idx >> 9;            // 0 = K, 1 = V
            int row = (idx >> 3) & 63;
            int cc  = idx & 7;
            int gk  = kc + row;
            bool valid = gk < SEQ;
            const __half* sp = m ? g_Vh : g_Kh;
            cp_async16(sb + QTILEB + stage * KVBUF + m * KTILEB + row * KROWB + cc * 16,
                       sp + base + (size_t)(valid ? gk : 0) * HDIM + cc * 8, valid);
        }
        CP_COMMIT();
    };
    issue_kv(q0, 0);

    // Q fragments (warp wid owns rows wid*16 .. wid*16+15)
    CP_WAIT(1);
    __syncthreads();
    uint32_t qh[4][4];
#pragma unroll
    for (int ks = 0; ks < 4; ks++)
        ldsm_x4(qh[ks], sb + (wid * 16 + (lane & 15)) * KROWB + ks * 32 + (lane >> 4) * 16);

    float o[8][4];
#pragma unroll
    for (int vi = 0; vi < 8; vi++)
#pragma unroll
        for (int r = 0; r < 4; r++) o[vi][r] = 0.f;
    float m0 = -FLT_MAX, m1 = -FLT_MAX, l0 = 0.f, l1 = 0.f;

    const int wrow0 = q0 + wid * 16;          // warp's first query row
    const int qrow0 = wrow0 + (lane >> 2);
    const int nkt = (SEQ - q0 + 63) / 64;

    for (int kt = 0; kt < nkt; kt++) {
        const int kc = q0 + kt * 64;
        const int stage = kt & 1;
        CP_WAIT(0);
        __syncthreads();
        if (kt + 1 < nkt) issue_kv(kc + 64, stage ^ 1);
        const uint32_t kb = sb + QTILEB + stage * KVBUF;

        // Whole tile below this warp's rows -> fully masked -> skip
        if (kc + 64 > wrow0) {
            // ---- S = Q K^T
            float s[8][4];
#pragma unroll
            for (int ni = 0; ni < 8; ni++)
#pragma unroll
                for (int r = 0; r < 4; r++) s[ni][r] = 0.f;
#pragma unroll
            for (int ks = 0; ks < 4; ks++) {
#pragma unroll
                for (int nip = 0; nip < 4; nip++) {
                    uint32_t kf[4];
                    uint32_t a = kb + (nip * 16 + (lane >> 4) * 8 + (lane & 7)) * KROWB
                               + ks * 32 + ((lane >> 3) & 1) * 16;
                    ldsm_x4(kf, a);
                    mma16816h(s[2 * nip],     qh[ks], kf);
                    mma16816h(s[2 * nip + 1], qh[ks], kf + 2);
                }
            }

            // ---- mask (tile overlaps diagonal for this warp, or SEQ edge)
            if (kc < wrow0 + 16 || kc + 64 > SEQ) {
#pragma unroll
                for (int ni = 0; ni < 8; ni++)
#pragma unroll
                    for (int r = 0; r < 4; r++) {
                        int key = kc + ni * 8 + 2 * (lane & 3) + (r & 1);
                        int qq  = qrow0 + (r >> 1) * 8;
                        if (key < qq || key >= SEQ) s[ni][r] = -FLT_MAX;
                    }
            }

            // ---- online softmax
            float t0 = -FLT_MAX, t1 = -FLT_MAX;
#pragma unroll
            for (int ni = 0; ni < 8; ni++) {
                t0 = fmaxf(t0, fmaxf(s[ni][0], s[ni][1]));
                t1 = fmaxf(t1, fmaxf(s[ni][2], s[ni][3]));
            }
            t0 = fmaxf(t0, __shfl_xor_sync(0xffffffffu, t0, 1));
            t0 = fmaxf(t0, __shfl_xor_sync(0xffffffffu, t0, 2));
            t1 = fmaxf(t1, __shfl_xor_sync(0xffffffffu, t1, 1));
            t1 = fmaxf(t1, __shfl_xor_sync(0xffffffffu, t1, 2));
            float mn0 = fmaxf(m0, t0), mn1 = fmaxf(m1, t1);
            float c0 = __expf((m0 - mn0) * SCALE);
            float c1 = __expf((m1 - mn1) * SCALE);
            m0 = mn0; m1 = mn1;
            l0 *= c0;  l1 *= c1;
#pragma unroll
            for (int vi = 0; vi < 8; vi++) {
                o[vi][0] *= c0; o[vi][1] *= c0;
                o[vi][2] *= c1; o[vi][3] *= c1;
            }

            // ---- P = exp, pack fp16 a-fragments
            uint32_t pa[4][4];
#pragma unroll
            for (int ni = 0; ni < 8; ni++) {
                float p0 = __expf((s[ni][0] - m0) * SCALE);
                float p1 = __expf((s[ni][1] - m0) * SCALE);
                float p2 = __expf((s[ni][2] - m1) * SCALE);
                float p3 = __expf((s[ni][3] - m1) * SCALE);
                l0 += p0 + p1;  l1 += p2 + p3;
                int kj = ni >> 1;
                int rg = (ni & 1) * 2;
                pa[kj][rg]     = h2_bits(p0, p1);
                pa[kj][rg + 1] = h2_bits(p2, p3);
            }

            // ---- O += P V  (V frags via ldmatrix.trans)
#pragma unroll
            for (int kj = 0; kj < 4; kj++) {
#pragma unroll
                for (int vip = 0; vip < 4; vip++) {
                    uint32_t vf[4];
                    uint32_t a = kb + KTILEB
                               + (kj * 16 + ((lane >> 3) & 1) * 8 + (lane & 7)) * KROWB
                               + vip * 32 + (lane >> 4) * 16;
                    ldsm_x4t(vf, a);
                    mma16816h(o[2 * vip],     pa[kj], vf);
                    mma16816h(o[2 * vip + 1], pa[kj], vf + 2);
                }
            }
        }
    }

    // ---- epilogue
    l0 += __shfl_xor_sync(0xffffffffu, l0, 1);
    l0 += __shfl_xor_sync(0xffffffffu, l0, 2);
    l1 += __shfl_xor_sync(0xffffffffu, l1, 1);
    l1 += __shfl_xor_sync(0xffffffffu, l1, 2);
    float inv0 = 1.f / l0, inv1 = 1.f / l1;

    const int b = bh / NHEAD, h = bh - b * NHEAD;
#pragma unroll
    for (int half = 0; half < 2; half++) {
        int q = q0 + wid * 16 + (lane >> 2) + half * 8;
        if (q >= SEQ) continue;
        size_t rowb = ((size_t)(b * SEQ + q)) * DMODEL + h * HDIM;
        float inv = half ? inv1 : inv0;
#pragma unroll
        for (int vi = 0; vi < 8; vi++) {
            int d = vi * 8 + 2 * (lane & 3);
            *(uint32_t*)(g_ch + rowb + d) =
                h2_bits(o[vi][half * 2 + 0] * inv, o[vi][half * 2 + 1] * inv);
        }
    }
}

// ---------------------------------------------------------------------------
extern "C" void kernel_launch(void* const* d_in, const int* in_sizes, int n_in,
                              void* d_out, int out_size)
{
    (void)in_sizes; (void)n_in; (void)out_size;
    const float* x  = (const float*)d_in[0];
    const float* Wq = (const float*)d_in[1];
    const float* bq = (const float*)d_in[2];
    const float* Wk = (const float*)d_in[3];
    const float* bk = (const float*)d_in[4];
    const float* Wv = (const float*)d_in[5];
    const float* bv = (const float*)d_in[6];
    const float* Wo = (const float*)d_in[7];
    const float* bo = (const float*)d_in[8];
    float* out = (float*)d_out;

    cudaFuncSetAttribute(gemm_tc<1>, cudaFuncAttributeMaxDynamicSharedMemorySize, GEMM_SMEM);
    cudaFuncSetAttribute(gemm_tc<0>, cudaFuncAttributeMaxDynamicSharedMemorySize, GEMM_SMEM);
    cudaFuncSetAttribute(attn_mma,   cudaFuncAttributeMaxDynamicSharedMemorySize, ATT_SMEM);

    // Single fused conversion launch
    to_fp16_all<<<(CVT_TOTAL + 255) / 256, 256>>>(x, Wq, Wk, Wv, Wo);

    // Fused QKV projection (18 n-tiles of 128 = 3 matrices x 6)
    gemm_tc<1><<<dim3(18, (MROWS + 127) / 128), 128, GEMM_SMEM>>>(bq, bk, bv, nullptr);

    // MMA flash attention (128-query tiles)
    attn_mma<<<dim3((SEQ + 127) / 128, BATCH * NHEAD), 256, ATT_SMEM>>>();

    // Output projection (6 n-tiles of 128)
    gemm_tc<0><<<dim3(6, (MROWS + 127) / 128), 128, GEMM_SMEM>>>(bo, nullptr, nullptr, out);
}

// round 13
// speedup vs baseline: 1.2695x; 1.0609x over previous
#include <cuda_runtime.h>
#include <cuda_fp16.h>
#include <float.h>
#include <math.h>
#include <cstdint>

// Problem constants
#define BATCH  32
#define SEQ    577
#define DMODEL 768
#define NHEAD  12
#define HDIM   64
#define MROWS  (BATCH * SEQ)                  // 18464
#define ELEMS  (MROWS * DMODEL)               // 14,180,352
#define WSZ    (DMODEL * DMODEL)              // 589,824

// fp16 scratch
__device__ __half g_xh[ELEMS];      // x
__device__ __half g_ch[ELEMS];      // ctx (attention output)
__device__ __half g_wh[4 * WSZ];    // Wq, Wk, Wv, Wo (contiguous)
__device__ __half g_Qh[ELEMS];      // [B,H,N,64]
__device__ __half g_Kh[ELEMS];
__device__ __half g_Vh[ELEMS];

// ---------------------------------------------------------------------------
// PTX helpers (plain sm_103-safe)
// ---------------------------------------------------------------------------
__device__ __forceinline__ uint32_t smem_u32(const void* p) {
    uint32_t a;
    asm("{ .reg .u64 t; cvta.to.shared.u64 t, %1; cvt.u32.u64 %0, t; }" : "=r"(a) : "l"(p));
    return a;
}
__device__ __forceinline__ void cp_async16(uint32_t dst, const void* src, bool valid) {
    int sz = valid ? 16 : 0;
    asm volatile("cp.async.cg.shared.global [%0], [%1], 16, %2;"
                 :: "r"(dst), "l"(src), "r"(sz));
}
#define CP_COMMIT() asm volatile("cp.async.commit_group;" ::: "memory")
#define CP_WAIT(N)  asm volatile("cp.async.wait_group %0;" :: "n"(N) : "memory")

__device__ __forceinline__ void ldsm_x4(uint32_t* r, uint32_t addr) {
    asm volatile("ldmatrix.sync.aligned.m8n8.x4.shared.b16 {%0,%1,%2,%3}, [%4];"
                 : "=r"(r[0]), "=r"(r[1]), "=r"(r[2]), "=r"(r[3]) : "r"(addr));
}
__device__ __forceinline__ void ldsm_x4t(uint32_t* r, uint32_t addr) {
    asm volatile("ldmatrix.sync.aligned.m8n8.x4.trans.shared.b16 {%0,%1,%2,%3}, [%4];"
                 : "=r"(r[0]), "=r"(r[1]), "=r"(r[2]), "=r"(r[3]) : "r"(addr));
}
__device__ __forceinline__ void mma16816h(float* c, const uint32_t* a, const uint32_t* b) {
    asm volatile(
        "mma.sync.aligned.m16n8k16.row.col.f32.f16.f16.f32 "
        "{%0,%1,%2,%3}, {%4,%5,%6,%7}, {%8,%9}, {%0,%1,%2,%3};"
        : "+f"(c[0]), "+f"(c[1]), "+f"(c[2]), "+f"(c[3])
        : "r"(a[0]), "r"(a[1]), "r"(a[2]), "r"(a[3]), "r"(b[0]), "r"(b[1]));
}
__device__ __forceinline__ uint32_t h2_bits(float a, float b) {
    __half2 v = __floats2half2_rn(a, b);
    return *(uint32_t*)&v;
}

// ---------------------------------------------------------------------------
// Fused fp32 -> fp16 conversion: x then Wq,Wk,Wv,Wo (one launch).
// ---------------------------------------------------------------------------
#define XN4 (ELEMS / 4)     // 3,545,088
#define WN4 (WSZ / 4)       // 147,456
#define CVT_TOTAL (XN4 + 4 * WN4)

__global__ void to_fp16_all(const float* __restrict__ x,  const float* __restrict__ wq,
                            const float* __restrict__ wk, const float* __restrict__ wv,
                            const float* __restrict__ wo)
{
    int i = blockIdx.x * blockDim.x + threadIdx.x;
    if (i >= CVT_TOTAL) return;
    const float* src;
    __half* dst;
    int j;
    if (i < XN4) { src = x; dst = g_xh; j = i; }
    else {
        int r = i - XN4;
        int m = r / WN4;
        j = r - m * WN4;
        src = (m == 0) ? wq : (m == 1) ? wk : (m == 2) ? wv : wo;
        dst = g_wh + (size_t)m * WSZ;
    }
    float4 v = ((const float4*)src)[j];
    ((uint32_t*)dst)[2 * j]     = h2_bits(v.x, v.y);
    ((uint32_t*)dst)[2 * j + 1] = h2_bits(v.z, v.w);
}

// ---------------------------------------------------------------------------
// fp16 NT GEMM (mma.sync m16n8k16, fp32 accum).
// CTA tile 128x128, 4 warps (2m x 2n), warp tile 64x64.
// K blocked by 64 (12 k-blocks), 2-stage cp.async, 3 CTAs/SM.
// QKV=1: fused QKV. grid.x = 18 (3 mats x 6 n-tiles); A = g_xh.
//        Epilogue: bias, fp16 scatter into g_{Q,K,V}h as [B,H,N,64].
// QKV=0: out-projection. grid.x = 6; A = g_ch; fp32 store to outp.
// ---------------------------------------------------------------------------
#define BKG    64
#define NKB    (DMODEL / BKG)         // 12
#define ROWB   144                    // 64 fp16 = 128B + 16B pad
#define AMATB  (128 * ROWB)           // 18432
#define STAGEB (2 * AMATB)            // 36864 (A + B)
#define GEMM_SMEM (2 * STAGEB)        // 73728  -> 3 CTAs/SM

extern __shared__ char dynsmem[];

template<int QKV>
__global__ __launch_bounds__(128, 3)
void gemm_tc(const float* __restrict__ b0, const float* __restrict__ b1,
             const float* __restrict__ b2, float* __restrict__ outp)
{
    const int mat  = QKV ? (blockIdx.x / 6) : 3;
    const int colb = QKV ? ((blockIdx.x % 6) * 128) : (blockIdx.x * 128);
    const __half* A = QKV ? g_xh : g_ch;
    const __half* B = g_wh + (size_t)mat * WSZ;
    const float* bias = QKV ? (mat == 0 ? b0 : mat == 1 ? b1 : b2) : b0;

    const uint32_t sb = smem_u32(dynsmem);
    const int tid  = threadIdx.x;
    const int wid  = tid >> 5;
    const int lane = tid & 31;
    const int wm   = wid & 1;          // 2 m-slabs of 64
    const int wn   = wid >> 1;         // 2 n-slabs of 64
    const int block_m = blockIdx.y * 128;

    float c[4][8][4];
#pragma unroll
    for (int mi = 0; mi < 4; mi++)
#pragma unroll
        for (int ni = 0; ni < 8; ni++)
#pragma unroll
            for (int r = 0; r < 4; r++) c[mi][ni][r] = 0.f;

    auto issue_load = [&](int kb, int buf) {
        const int k0 = kb * BKG;
        const uint32_t stg = sb + buf * STAGEB;
#pragma unroll
        for (int it = 0; it < 16; it++) {
            int idx = tid + it * 128;          // 0..2047
            int m   = idx >> 10;               // 0 = A, 1 = B
            int row = (idx >> 3) & 127;
            int cc  = idx & 7;
            if (m == 0) {
                int gr = block_m + row;
                bool valid = gr < MROWS;
                if (!valid) gr = 0;
                cp_async16(stg + row * ROWB + cc * 16,
                           A + (size_t)gr * DMODEL + k0 + cc * 8, valid);
            } else {
                cp_async16(stg + AMATB + row * ROWB + cc * 16,
                           B + (size_t)(colb + row) * DMODEL + k0 + cc * 8, true);
            }
        }
        CP_COMMIT();
    };

    issue_load(0, 0);

    for (int kb = 0; kb < NKB; kb++) {
        CP_WAIT(0);
        __syncthreads();   // all warps past previous compute; kb data visible
        if (kb + 1 < NKB) issue_load(kb + 1, (kb + 1) & 1);

        const uint32_t stg = sb + (kb & 1) * STAGEB;
#pragma unroll
        for (int kt = 0; kt < 4; kt++) {
            uint32_t afr[4][4];
            uint32_t bfr[4][4];
#pragma unroll
            for (int mi = 0; mi < 4; mi++) {
                int row  = wm * 64 + mi * 16 + (lane & 15);
                int kcol = kt * 16 + (lane >> 4) * 8;
                ldsm_x4(afr[mi], stg + row * ROWB + kcol * 2);
            }
#pragma unroll
            for (int nip = 0; nip < 4; nip++) {
                int brow = wn * 64 + nip * 16 + (lane >> 4) * 8 + (lane & 7);
                ldsm_x4(bfr[nip], stg + AMATB + brow * ROWB
                                  + kt * 32 + ((lane >> 3) & 1) * 16);
            }
#pragma unroll
            for (int mi = 0; mi < 4; mi++)
#pragma unroll
                for (int nip = 0; nip < 4; nip++) {
                    mma16816h(c[mi][2 * nip],     afr[mi], bfr[nip]);
                    mma16816h(c[mi][2 * nip + 1], afr[mi], bfr[nip] + 2);
                }
        }
    }

    __half* qkvd = (mat == 0) ? g_Qh : (mat == 1) ? g_Kh : g_Vh;
#pragma unroll
    for (int mi = 0; mi < 4; mi++) {
#pragma unroll
        for (int half = 0; half < 2; half++) {
            int gm = block_m + wm * 64 + mi * 16 + (lane >> 2) + half * 8;
            if (gm >= MROWS) continue;
            int b_idx = gm / SEQ;
            int n_idx = gm - b_idx * SEQ;
#pragma unroll
            for (int ni = 0; ni < 8; ni++) {
                int colg = colb + wn * 64 + ni * 8 + 2 * (lane & 3);
                float2 bv = *(const float2*)(bias + colg);
                float v0 = c[mi][ni][half * 2 + 0] + bv.x;
                float v1 = c[mi][ni][half * 2 + 1] + bv.y;
                if (QKV) {
                    int h = colg >> 6, hd = colg & 63;
                    size_t off = (((size_t)b_idx * NHEAD + h) * SEQ + n_idx) * HDIM + hd;
                    *(uint32_t*)(qkvd + off) = h2_bits(v0, v1);
                } else {
                    *(float2*)(outp + (size_t)gm * DMODEL + colg) = make_float2(v0, v1);
                }
            }
        }
    }
}

// ---------------------------------------------------------------------------
// MMA flash attention (fp16): anti-causal (k >= q), scale 1/sqrt(768).
// CTA = (b,h, 128-query tile); 8 warps x 16 rows; 64-key tiles, cp.async
// double-buffered. Per-warp whole-tile skip when all keys < warp's rows.
// ---------------------------------------------------------------------------
#define KROWB  144                    // 64 fp16 = 128B + 16B pad
#define QTILEB (128 * KROWB)          // 18432
#define KTILEB (64 * KROWB)           // 9216
#define KVBUF  (2 * KTILEB)           // K + V
#define ATT_SMEM (QTILEB + 2 * KVBUF) // 55296

__global__ __launch_bounds__(256, 2)
void attn_mma()
{
    const int bh  = blockIdx.y;
    const int q0  = blockIdx.x * 128;
    const int tid = threadIdx.x;
    const int wid = tid >> 5;
    const int lane = tid & 31;
    const uint32_t sb = smem_u32(dynsmem);
    const size_t base = (size_t)bh * SEQ * HDIM;
    const float SCALE = 0.03608439182435161f;   // 1/sqrt(768)

    // Q tile: 128 rows x 8 chunks = 1024 over 256 threads
#pragma unroll
    for (int it = 0; it < 4; it++) {
        int idx = tid + it * 256;
        int row = idx >> 3;
        int cc  = idx & 7;
        int gq  = q0 + row;
        bool valid = gq < SEQ;
        cp_async16(sb + row * KROWB + cc * 16,
                   g_Qh + base + (size_t)(valid ? gq : 0) * HDIM + cc * 8, valid);
    }
    CP_COMMIT();

    auto issue_kv = [&](int kc, int stage) {
#pragma unroll
        for (int it = 0; it < 4; it++) {
            int idx = tid + it * 256;      // 0..1023
            int m   = idx >> 9;            // 0 = K, 1 = V
            int row = (idx >> 3) & 63;
            int cc  = idx & 7;
            int gk  = kc + row;
            bool valid = gk < SEQ;
            const __half* sp = m ? g_Vh : g_Kh;
            cp_async16(sb + QTILEB + stage * KVBUF + m * KTILEB + row * KROWB + cc * 16,
                       sp + base + (size_t)(valid ? gk : 0) * HDIM + cc * 8, valid);
        }
        CP_COMMIT();
    };
    issue_kv(q0, 0);

    // Q fragments (warp wid owns rows wid*16 .. wid*16+15)
    CP_WAIT(1);
    __syncthreads();
    uint32_t qh[4][4];
#pragma unroll
    for (int ks = 0; ks < 4; ks++)
        ldsm_x4(qh[ks], sb + (wid * 16 + (lane & 15)) * KROWB + ks * 32 + (lane >> 4) * 16);

    float o[8][4];
#pragma unroll
    for (int vi = 0; vi < 8; vi++)
#pragma unroll
        for (int r = 0; r < 4; r++) o[vi][r] = 0.f;
    float m0 = -FLT_MAX, m1 = -FLT_MAX, l0 = 0.f, l1 = 0.f;

    const int wrow0 = q0 + wid * 16;          // warp's first query row
    const int qrow0 = wrow0 + (lane >> 2);
    const int nkt = (SEQ - q0 + 63) / 64;

    for (int kt = 0; kt < nkt; kt++) {
        const int kc = q0 + kt * 64;
        const int stage = kt & 1;
        CP_WAIT(0);
        __syncthreads();
        if (kt + 1 < nkt) issue_kv(kc + 64, stage ^ 1);
        const uint32_t kb = sb + QTILEB + stage * KVBUF;

        // Whole tile below this warp's rows -> fully masked -> skip
        if (kc + 64 > wrow0) {
            // ---- S = Q K^T
            float s[8][4];
#pragma unroll
            for (int ni = 0; ni < 8; ni++)
#pragma unroll
                for (int r = 0; r < 4; r++) s[ni][r] = 0.f;
#pragma unroll
            for (int ks = 0; ks < 4; ks++) {
#pragma unroll
                for (int nip = 0; nip < 4; nip++) {
                    uint32_t kf[4];
                    uint32_t a = kb + (nip * 16 + (lane >> 4) * 8 + (lane & 7)) * KROWB
                               + ks * 32 + ((lane >> 3) & 1) * 16;
                    ldsm_x4(kf, a);
                    mma16816h(s[2 * nip],     qh[ks], kf);
                    mma16816h(s[2 * nip + 1], qh[ks], kf + 2);
                }
            }

            // ---- mask (tile overlaps diagonal for this warp, or SEQ edge)
            if (kc < wrow0 + 16 || kc + 64 > SEQ) {
#pragma unroll
                for (int ni = 0; ni < 8; ni++)
#pragma unroll
                    for (int r = 0; r < 4; r++) {
                        int key = kc + ni * 8 + 2 * (lane & 3) + (r & 1);
                        int qq  = qrow0 + (r >> 1) * 8;
                        if (key < qq || key >= SEQ) s[ni][r] = -FLT_MAX;
                    }
            }

            // ---- online softmax
            float t0 = -FLT_MAX, t1 = -FLT_MAX;
#pragma unroll
            for (int ni = 0; ni < 8; ni++) {
                t0 = fmaxf(t0, fmaxf(s[ni][0], s[ni][1]));
                t1 = fmaxf(t1, fmaxf(s[ni][2], s[ni][3]));
            }
            t0 = fmaxf(t0, __shfl_xor_sync(0xffffffffu, t0, 1));
            t0 = fmaxf(t0, __shfl_xor_sync(0xffffffffu, t0, 2));
            t1 = fmaxf(t1, __shfl_xor_sync(0xffffffffu, t1, 1));
            t1 = fmaxf(t1, __shfl_xor_sync(0xffffffffu, t1, 2));
            float mn0 = fmaxf(m0, t0), mn1 = fmaxf(m1, t1);
            float c0 = __expf((m0 - mn0) * SCALE);
            float c1 = __expf((m1 - mn1) * SCALE);
            m0 = mn0; m1 = mn1;
            l0 *= c0;  l1 *= c1;
#pragma unroll
            for (int vi = 0; vi < 8; vi++) {
                o[vi][0] *= c0; o[vi][1] *= c0;
                o[vi][2] *= c1; o[vi][3] *= c1;
            }

            // ---- P = exp, pack fp16 a-fragments
            uint32_t pa[4][4];
#pragma unroll
            for (int ni = 0; ni < 8; ni++) {
                float p0 = __expf((s[ni][0] - m0) * SCALE);
                float p1 = __expf((s[ni][1] - m0) * SCALE);
                float p2 = __expf((s[ni][2] - m1) * SCALE);
                float p3 = __expf((s[ni][3] - m1) * SCALE);
                l0 += p0 + p1;  l1 += p2 + p3;
                int kj = ni >> 1;
                int rg = (ni & 1) * 2;
                pa[kj][rg]     = h2_bits(p0, p1);
                pa[kj][rg + 1] = h2_bits(p2, p3);
            }

            // ---- O += P V  (V frags via ldmatrix.trans)
#pragma unroll
            for (int kj = 0; kj < 4; kj++) {
#pragma unroll
                for (int vip = 0; vip < 4; vip++) {
                    uint32_t vf[4];
                    uint32_t a = kb + KTILEB
                               + (kj * 16 + ((lane >> 3) & 1) * 8 + (lane & 7)) * KROWB
                               + vip * 32 + (lane >> 4) * 16;
                    ldsm_x4t(vf, a);
                    mma16816h(o[2 * vip],     pa[kj], vf);
                    mma16816h(o[2 * vip + 1], pa[kj], vf + 2);
                }
            }
        }
    }

    // ---- epilogue
    l0 += __shfl_xor_sync(0xffffffffu, l0, 1);
    l0 += __shfl_xor_sync(0xffffffffu, l0, 2);
    l1 += __shfl_xor_sync(0xffffffffu, l1, 1);
    l1 += __shfl_xor_sync(0xffffffffu, l1, 2);
    float inv0 = 1.f / l0, inv1 = 1.f / l1;

    const int b = bh / NHEAD, h = bh - b * NHEAD;
#pragma unroll
    for (int half = 0; half < 2; half++) {
        int q = q0 + wid * 16 + (lane >> 2) + half * 8;
        if (q >= SEQ) continue;
        size_t rowb = ((size_t)(b * SEQ + q)) * DMODEL + h * HDIM;
        float inv = half ? inv1 : inv0;
#pragma unroll
        for (int vi = 0; vi < 8; vi++) {
            int d = vi * 8 + 2 * (lane & 3);
            *(uint32_t*)(g_ch + rowb + d) =
                h2_bits(o[vi][half * 2 + 0] * inv, o[vi][half * 2 + 1] * inv);
        }
    }
}

// ---------------------------------------------------------------------------
extern "C" void kernel_launch(void* const* d_in, const int* in_sizes, int n_in,
                              void* d_out, int out_size)
{
    (void)in_sizes; (void)n_in; (void)out_size;
    const float* x  = (const float*)d_in[0];
    const float* Wq = (const float*)d_in[1];
    const float* bq = (const float*)d_in[2];
    const float* Wk = (const float*)d_in[3];
    const float* bk = (const float*)d_in[4];
    const float* Wv = (const float*)d_in[5];
    const float* bv = (const float*)d_in[6];
    const float* Wo = (const float*)d_in[7];
    const float* bo = (const float*)d_in[8];
    float* out = (float*)d_out;

    cudaFuncSetAttribute(gemm_tc<1>, cudaFuncAttributeMaxDynamicSharedMemorySize, GEMM_SMEM);
    cudaFuncSetAttribute(gemm_tc<0>, cudaFuncAttributeMaxDynamicSharedMemorySize, GEMM_SMEM);
    cudaFuncSetAttribute(attn_mma,   cudaFuncAttributeMaxDynamicSharedMemorySize, ATT_SMEM);

    // Single fused conversion launch
    to_fp16_all<<<(CVT_TOTAL + 255) / 256, 256>>>(x, Wq, Wk, Wv, Wo);

    // Fused QKV projection (18 n-tiles of 128 = 3 matrices x 6)
    gemm_tc<1><<<dim3(18, (MROWS + 127) / 128), 128, GEMM_SMEM>>>(bq, bk, bv, nullptr);

    // MMA flash attention (128-query tiles)
    attn_mma<<<dim3((SEQ + 127) / 128, BATCH * NHEAD), 256, ATT_SMEM>>>();

    // Output projection (6 n-tiles of 128)
    gemm_tc<0><<<dim3(6, (MROWS + 127) / 128), 128, GEMM_SMEM>>>(bo, nullptr, nullptr, out);
}